// round 6
// baseline (speedup 1.0000x reference)
#include <cuda_runtime.h>
#include <cstddef>

// mRoPE flat elementwise, 4 units/thread, front-batched loads.
// q[T, 32*128], k[T, 8*128], cos/sin[3, T, 64]; half = 64.
// sections (32,32,32): j<32 -> plane 0, j in [32,64) -> plane 1.
// out[j]    = x[j]*c[j]   - x[j+64]*s[j]
// out[j+64] = x[j+64]*c[j] + x[j]*s[j]

#define T_TOK 16384
#define HALF  64
#define NQH   32
#define NKH   8
#define HS    128

#define Q_UNITS (T_TOK * NQH * (HALF / 4))   // 8,388,608
#define K_UNITS (T_TOK * NKH * (HALF / 4))   // 2,097,152
#define UPB     1024                          // units per block (4/thread)
#define Q_BLOCKS (Q_UNITS / UPB)              // 8192
#define K_BLOCKS (K_UNITS / UPB)              // 2048

struct UnitAddr {
    size_t off;     // element offset into src/dst
    size_t cs_off;  // element offset into cos/sin
};

__device__ __forceinline__ UnitAddr decode_q(int i)
{
    const int t  = i >> 9;            // 512 units per token
    const int r  = i & 511;
    const int j4 = r & 15;
    UnitAddr u;
    u.off    = ((size_t)t << 12) + ((size_t)(r >> 4) << 7) + (j4 << 2);
    u.cs_off = (size_t)(j4 >> 3) * (T_TOK * HALF) + ((size_t)t << 6) + (j4 << 2);
    return u;
}

__device__ __forceinline__ UnitAddr decode_k(int i)
{
    const int t  = i >> 7;            // 128 units per token
    const int r  = i & 127;
    const int j4 = r & 15;
    UnitAddr u;
    u.off    = ((size_t)t << 10) + ((size_t)(r >> 4) << 7) + (j4 << 2);
    u.cs_off = (size_t)(j4 >> 3) * (T_TOK * HALF) + ((size_t)t << 6) + (j4 << 2);
    return u;
}

__device__ __forceinline__ void rope_math(const float4& a, const float4& b,
                                          const float4& c, const float4& s,
                                          float4& o1, float4& o2)
{
    o1.x = fmaf(a.x, c.x, -b.x * s.x);
    o1.y = fmaf(a.y, c.y, -b.y * s.y);
    o1.z = fmaf(a.z, c.z, -b.z * s.z);
    o1.w = fmaf(a.w, c.w, -b.w * s.w);
    o2.x = fmaf(b.x, c.x,  a.x * s.x);
    o2.y = fmaf(b.y, c.y,  a.y * s.y);
    o2.z = fmaf(b.z, c.z,  a.z * s.z);
    o2.w = fmaf(b.w, c.w,  a.w * s.w);
}

__device__ __forceinline__ void rope_quad(const float* __restrict__ src,
                                          float* __restrict__ dst,
                                          const float* __restrict__ cosp,
                                          const float* __restrict__ sinp,
                                          UnitAddr u0, UnitAddr u1,
                                          UnitAddr u2, UnitAddr u3)
{
    // Front-batch all 16 loads (independent -> high MLP).
    const float4 a0 = __ldcs(reinterpret_cast<const float4*>(src + u0.off));
    const float4 b0 = __ldcs(reinterpret_cast<const float4*>(src + u0.off + HALF));
    const float4 a1 = __ldcs(reinterpret_cast<const float4*>(src + u1.off));
    const float4 b1 = __ldcs(reinterpret_cast<const float4*>(src + u1.off + HALF));
    const float4 a2 = __ldcs(reinterpret_cast<const float4*>(src + u2.off));
    const float4 b2 = __ldcs(reinterpret_cast<const float4*>(src + u2.off + HALF));
    const float4 a3 = __ldcs(reinterpret_cast<const float4*>(src + u3.off));
    const float4 b3 = __ldcs(reinterpret_cast<const float4*>(src + u3.off + HALF));
    const float4 c0 = __ldg (reinterpret_cast<const float4*>(cosp + u0.cs_off));
    const float4 s0 = __ldg (reinterpret_cast<const float4*>(sinp + u0.cs_off));
    const float4 c1 = __ldg (reinterpret_cast<const float4*>(cosp + u1.cs_off));
    const float4 s1 = __ldg (reinterpret_cast<const float4*>(sinp + u1.cs_off));
    const float4 c2 = __ldg (reinterpret_cast<const float4*>(cosp + u2.cs_off));
    const float4 s2 = __ldg (reinterpret_cast<const float4*>(sinp + u2.cs_off));
    const float4 c3 = __ldg (reinterpret_cast<const float4*>(cosp + u3.cs_off));
    const float4 s3 = __ldg (reinterpret_cast<const float4*>(sinp + u3.cs_off));

    float4 o1a, o2a, o1b, o2b, o1c, o2c, o1d, o2d;
    rope_math(a0, b0, c0, s0, o1a, o2a);
    rope_math(a1, b1, c1, s1, o1b, o2b);
    rope_math(a2, b2, c2, s2, o1c, o2c);
    rope_math(a3, b3, c3, s3, o1d, o2d);

    *reinterpret_cast<float4*>(dst + u0.off)        = o1a;
    *reinterpret_cast<float4*>(dst + u0.off + HALF) = o2a;
    *reinterpret_cast<float4*>(dst + u1.off)        = o1b;
    *reinterpret_cast<float4*>(dst + u1.off + HALF) = o2b;
    *reinterpret_cast<float4*>(dst + u2.off)        = o1c;
    *reinterpret_cast<float4*>(dst + u2.off + HALF) = o2c;
    *reinterpret_cast<float4*>(dst + u3.off)        = o1d;
    *reinterpret_cast<float4*>(dst + u3.off + HALF) = o2d;
}

__global__ __launch_bounds__(256)
void mrope_flat4_kernel(const float* __restrict__ q,
                        const float* __restrict__ k,
                        const float* __restrict__ cosp,
                        const float* __restrict__ sinp,
                        float* __restrict__ qo,
                        float* __restrict__ ko)
{
    const int bid = blockIdx.x;
    const int tid = threadIdx.x;

    if (bid < Q_BLOCKS) {
        const int base = bid * UPB;
        rope_quad(q, qo, cosp, sinp,
                  decode_q(base + tid),       decode_q(base + 256 + tid),
                  decode_q(base + 512 + tid), decode_q(base + 768 + tid));
    } else {
        const int base = (bid - Q_BLOCKS) * UPB;
        rope_quad(k, ko, cosp, sinp,
                  decode_k(base + tid),       decode_k(base + 256 + tid),
                  decode_k(base + 512 + tid), decode_k(base + 768 + tid));
    }
}

extern "C" void kernel_launch(void* const* d_in, const int* in_sizes, int n_in,
                              void* d_out, int out_size)
{
    const float* q    = (const float*)d_in[0];
    const float* k    = (const float*)d_in[1];
    const float* cosp = (const float*)d_in[2];
    const float* sinp = (const float*)d_in[3];

    float* qo = (float*)d_out;
    float* ko = qo + (size_t)T_TOK * NQH * HS;

    mrope_flat4_kernel<<<Q_BLOCKS + K_BLOCKS, 256>>>(q, k, cosp, sinp, qo, ko);
}

// round 7
// speedup vs baseline: 1.0237x; 1.0237x over previous
#include <cuda_runtime.h>
#include <cstddef>
#include <cstdint>

// mRoPE flat elementwise with 256-bit global accesses (sm_103a LDG.E.256).
// q[T, 32*128], k[T, 8*128], cos/sin[3, T, 64]; half = 64.
// sections (32,32,32): j<32 -> plane 0, j in [32,64) -> plane 1.
// out[j]    = x[j]*c[j]   - x[j+64]*s[j]
// out[j+64] = x[j+64]*c[j] + x[j]*s[j]
//
// Chunk = 8 consecutive floats of a head's first half + matching 8 of the
// second half. One chunk per thread: 4x v8 loads (128B), 2x v8 stores (64B).

#define T_TOK 16384
#define HALF  64
#define NQH   32
#define NKH   8
#define HS    128

#define Q_CHUNKS (T_TOK * NQH * (HALF / 8))   // 4,194,304
#define K_CHUNKS (T_TOK * NKH * (HALF / 8))   // 1,048,576
#define Q_BLOCKS (Q_CHUNKS / 256)             // 16384
#define K_BLOCKS (K_CHUNKS / 256)             // 4096

struct V8 { uint32_t r[8]; };

__device__ __forceinline__ V8 ldg256(const float* p)
{
    V8 v;
    asm volatile("ld.global.nc.v8.b32 {%0,%1,%2,%3,%4,%5,%6,%7}, [%8];"
                 : "=r"(v.r[0]), "=r"(v.r[1]), "=r"(v.r[2]), "=r"(v.r[3]),
                   "=r"(v.r[4]), "=r"(v.r[5]), "=r"(v.r[6]), "=r"(v.r[7])
                 : "l"(p));
    return v;
}

__device__ __forceinline__ void stg256(float* p, const V8& v)
{
    asm volatile("st.global.v8.b32 [%0], {%1,%2,%3,%4,%5,%6,%7,%8};"
                 :: "l"(p),
                    "r"(v.r[0]), "r"(v.r[1]), "r"(v.r[2]), "r"(v.r[3]),
                    "r"(v.r[4]), "r"(v.r[5]), "r"(v.r[6]), "r"(v.r[7])
                 : "memory");
}

__device__ __forceinline__ void rope_chunk(const float* __restrict__ src,
                                           float* __restrict__ dst,
                                           const float* __restrict__ cosp,
                                           const float* __restrict__ sinp,
                                           size_t off, size_t cs_off)
{
    const V8 a = ldg256(src + off);          // x1
    const V8 b = ldg256(src + off + HALF);   // x2
    const V8 c = ldg256(cosp + cs_off);
    const V8 s = ldg256(sinp + cs_off);

    V8 o1, o2;
#pragma unroll
    for (int e = 0; e < 8; e++) {
        const float af = __uint_as_float(a.r[e]);
        const float bf = __uint_as_float(b.r[e]);
        const float cf = __uint_as_float(c.r[e]);
        const float sf = __uint_as_float(s.r[e]);
        o1.r[e] = __float_as_uint(fmaf(af, cf, -bf * sf));
        o2.r[e] = __float_as_uint(fmaf(bf, cf,  af * sf));
    }

    stg256(dst + off,        o1);
    stg256(dst + off + HALF, o2);
}

__global__ __launch_bounds__(256)
void mrope_v8_kernel(const float* __restrict__ q,
                     const float* __restrict__ k,
                     const float* __restrict__ cosp,
                     const float* __restrict__ sinp,
                     float* __restrict__ qo,
                     float* __restrict__ ko)
{
    const int bid = blockIdx.x;
    const int tid = threadIdx.x;

    if (bid < Q_BLOCKS) {
        const int i  = (bid << 8) + tid;   // q chunk index
        const int t  = i >> 8;             // 256 chunks/token
        const int r  = i & 255;
        const int j8 = r & 7;              // chunk within half (0..7)
        const size_t off    = ((size_t)t << 12) + ((size_t)(r >> 3) << 7) + (j8 << 3);
        const size_t cs_off = (size_t)(j8 >> 2) * (T_TOK * HALF) + ((size_t)t << 6) + (j8 << 3);
        rope_chunk(q, qo, cosp, sinp, off, cs_off);
    } else {
        const int i  = ((bid - Q_BLOCKS) << 8) + tid;  // k chunk index
        const int t  = i >> 6;             // 64 chunks/token
        const int r  = i & 63;
        const int j8 = r & 7;
        const size_t off    = ((size_t)t << 10) + ((size_t)(r >> 3) << 7) + (j8 << 3);
        const size_t cs_off = (size_t)(j8 >> 2) * (T_TOK * HALF) + ((size_t)t << 6) + (j8 << 3);
        rope_chunk(k, ko, cosp, sinp, off, cs_off);
    }
}

extern "C" void kernel_launch(void* const* d_in, const int* in_sizes, int n_in,
                              void* d_out, int out_size)
{
    const float* q    = (const float*)d_in[0];
    const float* k    = (const float*)d_in[1];
    const float* cosp = (const float*)d_in[2];
    const float* sinp = (const float*)d_in[3];

    float* qo = (float*)d_out;
    float* ko = qo + (size_t)T_TOK * NQH * HS;

    mrope_v8_kernel<<<Q_BLOCKS + K_BLOCKS, 256>>>(q, k, cosp, sinp, qo, ko);
}